// round 1
// baseline (speedup 1.0000x reference)
#include <cuda_runtime.h>
#include <cstdint>

// UpsampleNearest4D: x (2,8,8,16,64,64) f32, scale=2 on axes 2..5.
// Output (2,8,16,32,128,128).
//
// Input-driven: one thread per input float2 (consecutive x pair).
// Each thread writes 8 float4 stores {a,a,b,b} covering the 2x2x2x2
// (t,z,y,x) duplication. All stores 16B-aligned, coalesced across lanes.
//
// Input geometry (collapsed): NC=16, T=8, Z=16, Y=64, X=64 floats
//   -> per row 32 float2 loads.
// Output geometry: NC=16, OT=16, OZ=32, OY=128, OX=128 floats
//   -> per row 32 float4 stores.

__global__ __launch_bounds__(256) void upsample4d_kernel(
    const float2* __restrict__ in, float4* __restrict__ out)
{
    unsigned idx = blockIdx.x * 256u + threadIdx.x;   // [0, 4194304)

    unsigned x2 = idx & 31u;            // float2 column within input row
    unsigned r  = idx >> 5;
    unsigned y  = r & 63u;  r >>= 6;
    unsigned z  = r & 15u;  r >>= 4;
    unsigned t  = r & 7u;   r >>= 3;
    unsigned nc = r;                    // [0,16)

    float2 v = in[idx];
    float4 o = make_float4(v.x, v.x, v.y, v.y);

    // Output strides in float4 units: row = 128/4 = 32
    const unsigned SY = 32u;                 // one output row
    const unsigned SZ = 128u * 32u;          // OY rows
    const unsigned ST = 32u * 128u * 32u;    // OZ * OY rows

    unsigned base = ((((nc * 16u + 2u * t) * 32u + 2u * z) * 128u + 2u * y) * 32u) + x2;

    out[base]                = o;
    out[base + SY]           = o;
    out[base + SZ]           = o;
    out[base + SZ + SY]      = o;
    out[base + ST]           = o;
    out[base + ST + SY]      = o;
    out[base + ST + SZ]      = o;
    out[base + ST + SZ + SY] = o;
}

extern "C" void kernel_launch(void* const* d_in, const int* in_sizes, int n_in,
                              void* d_out, int out_size)
{
    const float2* in = (const float2*)d_in[0];
    float4* out = (float4*)d_out;

    // 8,388,608 input floats -> 4,194,304 float2 threads
    const unsigned n_threads = 8u * 1024u * 1024u / 2u;
    upsample4d_kernel<<<n_threads / 256u, 256u>>>(in, out);
}